// round 6
// baseline (speedup 1.0000x reference)
#include <cuda_runtime.h>
#include <cstdint>

#define PB 4
#define PN 16384
#define PS 2048
#define PC 64
#define PK 33
#define PNS 32
#define JTOT (PS * PK)        // 67584
#define OUTC (6 + PC)         // 70
#define GR 10
#define NC (GR * GR * GR)     // 1000
#define BPB 16                // hist/scatter blocks per batch
#define NBLK (PB * BPB)       // 64
#define PTS_PER_BLK (PN / BPB)  // 1024
#define NB 512                // persistent mega-kernel blocks (co-resident: cap >= 592)
#define NTILES 1024           // 64x64 transpose tiles: (PN/64) * PB
#define T1 (NB - NBLK)        // 448 tiles in phase 1
#define CAP 256

__device__ int    g_idx[PB * PS * PK];
__device__ float4 g_featT4[(size_t)PB * PN * PC / 4];
__device__ int    g_cellStart[PB * (NC + 1)];
__device__ int    g_hist[NBLK * NC];
__device__ int    g_blockBase[NBLK * NC];
__device__ float4 g_pts[PB * PN];
__device__ unsigned g_bar_cnt;   // zero-init; returns to 0 after each barrier
__device__ unsigned g_bar_gen;   // monotone across replays (relative compare)

__device__ __forceinline__ int cell_of(float x, float y, float z) {
    int ix = min((int)(x * 10.0f), GR - 1);
    int iy = min((int)(y * 10.0f), GR - 1);
    int iz = min((int)(z * 10.0f), GR - 1);
    return (iz * GR + iy) * GR + ix;
}

// Grid-wide generation barrier. All NB blocks are co-resident by construction.
__device__ __forceinline__ void grid_barrier() {
    __syncthreads();
    if (threadIdx.x == 0) {
        __threadfence();                       // publish our phase's writes
        volatile unsigned* vgen = &g_bar_gen;
        unsigned gen = *vgen;
        if (atomicAdd(&g_bar_cnt, 1u) == NB - 1) {
            g_bar_cnt = 0;                     // all arrived; reset before release
            __threadfence();
            atomicAdd(&g_bar_gen, 1u);         // release
        } else {
            while (*vgen == gen) __nanosleep(32);
        }
        __threadfence();
    }
    __syncthreads();
}

// One 64x64 transpose tile: features (B,C,N) -> g_featT4 (B,N,C)
__device__ __forceinline__ void do_tile(int tt, const float* __restrict__ f, float* tile) {
    int b  = tt >> 8;
    int n0 = (tt & 255) * 64;
    const float* fb = f + (size_t)b * PC * PN;
    float4*     ftb = g_featT4 + (size_t)b * PN * (PC / 4);
    int t  = threadIdx.x;
    int qd = t & 15;
    int r0 = t >> 4;
#pragma unroll
    for (int k = 0; k < 4; k++) {
        int c = r0 + k * 16;
        float4 v = *(const float4*)(fb + (size_t)c * PN + n0 + qd * 4);
        tile[c * 65 + qd * 4 + 0] = v.x;
        tile[c * 65 + qd * 4 + 1] = v.y;
        tile[c * 65 + qd * 4 + 2] = v.z;
        tile[c * 65 + qd * 4 + 3] = v.w;
    }
    __syncthreads();
#pragma unroll
    for (int k = 0; k < 4; k++) {
        int n = r0 + k * 16;
        float4 v;
        v.x = tile[(qd * 4 + 0) * 65 + n];
        v.y = tile[(qd * 4 + 1) * 65 + n];
        v.z = tile[(qd * 4 + 2) * 65 + n];
        v.w = tile[(qd * 4 + 3) * 65 + n];
        ftb[(size_t)(n0 + n) * (PC / 4) + qd] = v;
    }
    __syncthreads();   // tile smem reusable for the next tile in this phase
}

// ---------------------------------------------------------------------------
// Persistent mega-kernel: hist | transpose -> scan | transpose -> scatter -> ball
// ---------------------------------------------------------------------------
__global__ void __launch_bounds__(256, 4) mega_kernel(
    const float* __restrict__ xyz, const float* __restrict__ new_xyz,
    const float* __restrict__ features, const int* __restrict__ fps)
{
    __shared__ __align__(16) int sm[4160];   // 16640 B, reused per phase
    int blk = blockIdx.x;
    int t   = threadIdx.x;

    // ---- Phase 1: per-block histograms (blocks 0..63) | transpose tiles ----
    if (blk < NBLK) {
        for (int i = t; i < NC; i += 256) sm[i] = 0;
        __syncthreads();
        int b = blk >> 4;
        const float* xb = xyz + ((size_t)b * PN + (blk & 15) * PTS_PER_BLK) * 3;
#pragma unroll
        for (int k = 0; k < 4; k++) {
            const float* p = xb + 3 * (t + k * 256);
            atomicAdd(&sm[cell_of(p[0], p[1], p[2])], 1);
        }
        __syncthreads();
        for (int i = t; i < NC; i += 256) g_hist[blk * NC + i] = sm[i];
    } else {
        for (int tt = blk - NBLK; tt < T1; tt += NB - NBLK)
            do_tile(tt, features, (float*)sm);
    }
    grid_barrier();

    // ---- Phase 2: per-batch scan (blocks 0..3) | remaining transpose tiles ----
    if (blk < PB) {
        int b  = blk;
        int c0 = t * 4;
        int tot[4] = {0, 0, 0, 0};
#pragma unroll
        for (int j = 0; j < 4; j++) {
            int c = c0 + j;
            if (c < NC) {
                int ssum = 0;
#pragma unroll
                for (int i = 0; i < BPB; i++) ssum += g_hist[(b * BPB + i) * NC + c];
                tot[j] = ssum;
            }
        }
        int tsum = tot[0] + tot[1] + tot[2] + tot[3];
        sm[t] = tsum;
        __syncthreads();
#pragma unroll
        for (int off = 1; off < 256; off <<= 1) {
            int v = (t >= off) ? sm[t - off] : 0;
            __syncthreads();
            if (t >= off) sm[t] += v;
            __syncthreads();
        }
        int run = sm[t] - tsum;     // exclusive prefix over threads
        if (t == 255) g_cellStart[b * (NC + 1) + NC] = sm[255];
#pragma unroll
        for (int j = 0; j < 4; j++) {
            int c = c0 + j;
            if (c < NC) {
                g_cellStart[b * (NC + 1) + c] = run;
                int rb = run;
#pragma unroll
                for (int i = 0; i < BPB; i++) {
                    g_blockBase[(b * BPB + i) * NC + c] = rb;
                    rb += g_hist[(b * BPB + i) * NC + c];
                }
                run += tot[j];
            }
        }
    } else {
        for (int tt = T1 + (blk - PB); tt < NTILES; tt += NB - PB)
            do_tile(tt, features, (float*)sm);
    }
    grid_barrier();

    // ---- Phase 3: scatter (blocks 0..63) ----
    if (blk < NBLK) {
        for (int i = t; i < NC; i += 256) sm[i] = g_blockBase[blk * NC + i];
        __syncthreads();
        int b = blk >> 4;
        int nbase = (blk & 15) * PTS_PER_BLK;
        const float* xb = xyz + ((size_t)b * PN + nbase) * 3;
        float4* pb = g_pts + (size_t)b * PN;
#pragma unroll
        for (int k = 0; k < 4; k++) {
            int n = t + k * 256;
            const float* p = xb + 3 * n;
            float x = p[0], y = p[1], z = p[2];
            int pos = atomicAdd(&sm[cell_of(x, y, z)], 1);
            pb[pos] = make_float4(x, y, z, __int_as_float(nbase + n));
        }
    }
    grid_barrier();

    // ---- Phase 4: ball query, all warps; exactly 2 queries per warp ----
    int wi   = t >> 5;
    int lane = t & 31;
    int* wbuf = sm + wi * 264;     // 1056 B per warp, 16B-aligned
    const float R2 = 0.01f;        // (float)(0.1*0.1 in f64) == 0.01f
    const unsigned FULL = 0xffffffffu;

    for (int gw = blk * 8 + wi; gw < PB * PS; gw += NB * 8) {
        int b = gw >> 11;
        int s = gw & (PS - 1);
        const float* q = new_xyz + ((size_t)b * PS + s) * 3;
        float qx = q[0], qy = q[1], qz = q[2];
        int* out = g_idx + (size_t)gw * PK;
        if (lane == 0) out[0] = fps[b * PS + s];

        int cx = min((int)(qx * 10.0f), GR - 1);
        int cy = min((int)(qy * 10.0f), GR - 1);
        int cz = min((int)(qz * 10.0f), GR - 1);
        const float4* pts = g_pts + (size_t)b * PN;
        const int*    cst = g_cellStart + (size_t)b * (NC + 1);

        int cnt = 0;
        int z0 = max(cz - 1, 0), z1 = min(cz + 1, GR - 1);
        int y0 = max(cy - 1, 0), y1 = min(cy + 1, GR - 1);
        int x0 = max(cx - 1, 0), x1 = min(cx + 1, GR - 1);

        for (int zz = z0; zz <= z1; zz++) {
            for (int yy = y0; yy <= y1; yy++) {
                int cbase = (zz * GR + yy) * GR;
                int beg = cst[cbase + x0];
                int end = cst[cbase + x1 + 1];
                for (; beg < end; beg += 32) {
                    int i = beg + lane;
                    bool hit = false;
                    int pid = 0;
                    if (i < end) {
                        float4 v = pts[i];
                        float dx = __fsub_rn(qx, v.x);
                        float dy = __fsub_rn(qy, v.y);
                        float dz = __fsub_rn(qz, v.z);
                        float d2 = __fadd_rn(__fadd_rn(__fmul_rn(dx, dx), __fmul_rn(dy, dy)),
                                             __fmul_rn(dz, dz));
                        hit = d2 < R2;
                        pid = __float_as_int(v.w);
                    }
                    unsigned m = __ballot_sync(FULL, hit);
                    if (hit) {
                        int pos = cnt + __popc(m & ((1u << lane) - 1u));
                        if (pos < CAP) wbuf[pos] = pid;
                    }
                    cnt += __popc(m);
                }
            }
        }

        int M  = min(cnt, CAP);
        int Mp = (M + 3) & ~3;
        if (lane < Mp - M) wbuf[M + lane] = 0x7fffffff;
        __syncwarp();

        int minhit = 0x7fffffff;
        const int4* b4 = (const int4*)wbuf;
        for (int i = lane; i < M; i += 32) {
            int h = wbuf[i];
            minhit = min(minhit, h);
            int rank = 0;
            int nq = Mp >> 2;
            for (int j = 0; j < nq; j++) {
                int4 w = b4[j];
                rank += (w.x < h) + (w.y < h) + (w.z < h) + (w.w < h);
            }
            if (rank < PNS) out[1 + rank] = h;
        }
#pragma unroll
        for (int off = 16; off; off >>= 1)
            minhit = min(minhit, __shfl_xor_sync(FULL, minhit, off));
        int fill = (cnt == 0) ? 0 : minhit;
        int c = min(cnt, PNS);
        if (lane >= c) out[1 + lane] = fill;
        __syncwarp();
    }
}

// ---------------------------------------------------------------------------
// Gather + write: 128 j per block, 256 threads, 2112 blocks.
// ---------------------------------------------------------------------------
#define TJ 128

__global__ void __launch_bounds__(256) gather_write(const float* __restrict__ xyz,
                                                    const float* __restrict__ new_xyz,
                                                    float* __restrict__ out) {
    __shared__ float tile[TJ][PC + 1];
    __shared__ int   sn[TJ];
    __shared__ float sxyz[TJ][3];
    __shared__ float sctr[TJ][3];

    int bj  = blockIdx.x;
    int b   = bj / (JTOT / TJ);
    int j0  = (bj - b * (JTOT / TJ)) * TJ;
    int tid = threadIdx.x;

    if (tid < TJ) {
        int j = j0 + tid;
        int n = g_idx[(size_t)b * JTOT + j];
        sn[tid] = n;
        int s = j / PK;
        const float* p = xyz     + ((size_t)b * PN + n) * 3;
        const float* q = new_xyz + ((size_t)b * PS + s) * 3;
        float x = p[0], y = p[1], z = p[2];
        sxyz[tid][0] = x;         sxyz[tid][1] = y;         sxyz[tid][2] = z;
        sctr[tid][0] = x - q[0];  sctr[tid][1] = y - q[1];  sctr[tid][2] = z - q[2];
    }
    __syncthreads();

    const float4* ftb = g_featT4 + (size_t)b * PN * (PC / 4);
#pragma unroll
    for (int it = 0; it < 8; it++) {
        int lin = tid + it * 256;
        int jj  = lin >> 4;
        int qd  = lin & 15;
        float4 v = ftb[(size_t)sn[jj] * (PC / 4) + qd];
        tile[jj][qd * 4 + 0] = v.x;
        tile[jj][qd * 4 + 1] = v.y;
        tile[jj][qd * 4 + 2] = v.z;
        tile[jj][qd * 4 + 3] = v.w;
    }
    __syncthreads();

    float* ob = out + (size_t)b * OUTC * JTOT + j0;
#pragma unroll
    for (int it = 0; it < 3; it++) {
        int idx  = it * 256 + tid;
        int c    = idx >> 7;
        int jpos = idx & (TJ - 1);
        float v = (c < 3) ? sxyz[jpos][c] : sctr[jpos][c - 3];
        ob[(size_t)c * JTOT + jpos] = v;
    }
#pragma unroll
    for (int it = 0; it < 32; it++) {
        int idx  = it * 256 + tid;
        int c    = idx >> 7;
        int jpos = idx & (TJ - 1);
        ob[(size_t)(6 + c) * JTOT + jpos] = tile[jpos][c];
    }
}

// ---------------------------------------------------------------------------
extern "C" void kernel_launch(void* const* d_in, const int* in_sizes, int n_in,
                              void* d_out, int out_size) {
    const float* xyz      = (const float*)d_in[0];
    const float* new_xyz  = (const float*)d_in[1];
    const float* features = (const float*)d_in[2];
    const int*   fps_idx  = (const int*)  d_in[3];
    float* out = (float*)d_out;

    mega_kernel<<<NB, 256>>>(xyz, new_xyz, features, fps_idx);
    gather_write<<<PB * (JTOT / TJ), 256>>>(xyz, new_xyz, out);
}